// round 11
// baseline (speedup 1.0000x reference)
#include <cuda_runtime.h>
#include <cuda_fp16.h>
#include <cstdint>

// ---------------------------------------------------------------------------
// Problem shape
// ---------------------------------------------------------------------------
#define B_  16
#define N_  1024
#define D_  768
#define H_  12
#define HS_ 64
#define M_  (B_*N_)     // 16384 token rows
#define L_  2
#define EPS_ 1e-6f
#define PI_ 3.14159265358979f

// ---------------------------------------------------------------------------
// Scratch
// ---------------------------------------------------------------------------
__device__ __half  g_xn [M_*D_];       // LN1(x)           (GEMM1 A)
__device__ __half  g_wvT[D_*D_];       // Wv^T [n=h*64+k][d]
__device__ __half  g_wfT[L_*D_*D_];    // Wf^T [l][n][d]
__device__ __half  g_vc [H_*N_*N_];    // v [h][b*64+k][j] (FFT input signals)
__device__ float2  g_af [H_*N_];       // FFT(alpha_h)/N, bit-reversed bins
__device__ float   g_y  [H_*N_*N_];    // conv result [h][b*64+k][i] (fp32)
__device__ float   g_x1 [M_*D_];       // residual x + y (fp32)
__device__ __half  g_x1h[M_*D_];       // fp16 copy        (FFN1 A)
__device__ __half  g_th [M_*D_];       // ffn gemm out (fp16)
__device__ __half  g_zh [M_*D_];       // swish(ln(t))     (FFN2 A)

// ---------------------------------------------------------------------------
// Helpers
// ---------------------------------------------------------------------------
__device__ __forceinline__ uint32_t smem_u32(const void* p) {
    uint32_t a;
    asm("{ .reg .u64 t; cvta.to.shared.u64 t, %1; cvt.u32.u64 %0, t; }"
        : "=r"(a) : "l"(p));
    return a;
}
__device__ __forceinline__ void ldsm_x4(uint32_t* d, uint32_t addr) {
    asm volatile("ldmatrix.sync.aligned.m8n8.x4.shared.b16 {%0,%1,%2,%3}, [%4];"
                 : "=r"(d[0]), "=r"(d[1]), "=r"(d[2]), "=r"(d[3]) : "r"(addr));
}
__device__ __forceinline__ void mma16816(float* d, const uint32_t* a,
                                         uint32_t b0, uint32_t b1) {
    asm volatile(
        "mma.sync.aligned.m16n8k16.row.col.f32.f16.f16.f32 "
        "{%0,%1,%2,%3}, {%4,%5,%6,%7}, {%8,%9}, {%0,%1,%2,%3};"
        : "+f"(d[0]), "+f"(d[1]), "+f"(d[2]), "+f"(d[3])
        : "r"(a[0]), "r"(a[1]), "r"(a[2]), "r"(a[3]), "r"(b0), "r"(b1));
}
__device__ __forceinline__ float2 cmul(float2 a, float2 b) {
    return make_float2(a.x*b.x - a.y*b.y, a.x*b.y + a.y*b.x);
}
#define CP_ASYNC(dst, src) \
    asm volatile("cp.async.cg.shared.global [%0], [%1], 16;" :: "r"(dst), "l"(src))
#define CP_COMMIT() asm volatile("cp.async.commit_group;" ::: "memory")
#define CP_WAIT(n)  asm volatile("cp.async.wait_group %0;" :: "n"(n) : "memory")

// ---------------------------------------------------------------------------
// Conversion kernels
// ---------------------------------------------------------------------------
__global__ void conv_wvT_kernel(const float* __restrict__ Wv) {
    int idx = blockIdx.x * blockDim.x + threadIdx.x;
    if (idx >= D_ * D_) return;
    int n = idx / D_, d = idx % D_;
    int h = n >> 6, k = n & 63;
    g_wvT[idx] = __float2half(Wv[((size_t)h * D_ + d) * HS_ + k]);
}
__global__ void conv_wfT_kernel(const float* __restrict__ Wf) {
    int idx = blockIdx.x * blockDim.x + threadIdx.x;
    if (idx >= L_ * D_ * D_) return;
    int l = idx / (D_ * D_);
    int r = idx % (D_ * D_);
    int n = r / D_, d = r % D_;
    g_wfT[idx] = __float2half(Wf[(size_t)l * D_ * D_ + (size_t)d * D_ + n]);
}

// ---------------------------------------------------------------------------
// FFT of alpha (forward DIF, bit-reversed output, pre-scaled by 1/N)
// ---------------------------------------------------------------------------
__global__ void __launch_bounds__(256) fft_alpha_kernel(const float* __restrict__ alpha) {
    __shared__ float2 s[N_];
    int h = blockIdx.x, tid = threadIdx.x;
    #pragma unroll
    for (int t = 0; t < 4; t++) {
        int j = tid + t * 256;
        s[j] = make_float2(alpha[h * N_ + j] * (1.f / N_), 0.f);
    }
    __syncthreads();
    for (int span = N_ / 2; span >= 1; span >>= 1) {
        #pragma unroll
        for (int t = 0; t < 2; t++) {
            int j = tid + t * 256;
            int pos = j & (span - 1);
            int i0 = ((j & ~(span - 1)) << 1) | pos;
            int i1 = i0 + span;
            float2 a = s[i0], b = s[i1];
            float dx = a.x - b.x, dy = a.y - b.y;
            float ang = -PI_ * (float)pos / (float)span;
            float sn, cs; __sincosf(ang, &sn, &cs);
            s[i0] = make_float2(a.x + b.x, a.y + b.y);
            s[i1] = make_float2(dx * cs - dy * sn, dx * sn + dy * cs);
        }
        __syncthreads();
    }
    #pragma unroll
    for (int t = 0; t < 4; t++) {
        int j = tid + t * 256;
        g_af[h * N_ + j] = s[j];
    }
}

// ---------------------------------------------------------------------------
// FFT convolution: two real v-rows packed as one complex signal.
// forward DIF -> pointwise (bit-rev aligned) -> inverse DIT -> y rows fp32
// ---------------------------------------------------------------------------
__global__ void __launch_bounds__(256) fft_conv_kernel() {
    __shared__ float2 s[N_];
    int h = blockIdx.x >> 9;           // /512
    int p = blockIdx.x & 511;
    int tid = threadIdx.x;

    const __half* vr = g_vc + ((size_t)h * N_ + 2 * p) * N_;
    #pragma unroll
    for (int t = 0; t < 4; t++) {
        int j = tid + t * 256;
        s[j] = make_float2(__half2float(vr[j]), __half2float(vr[j + N_]));
    }
    __syncthreads();

    // forward DIF
    for (int span = N_ / 2; span >= 1; span >>= 1) {
        #pragma unroll
        for (int t = 0; t < 2; t++) {
            int j = tid + t * 256;
            int pos = j & (span - 1);
            int i0 = ((j & ~(span - 1)) << 1) | pos;
            int i1 = i0 + span;
            float2 a = s[i0], b = s[i1];
            float dx = a.x - b.x, dy = a.y - b.y;
            float ang = -PI_ * (float)pos / (float)span;
            float sn, cs; __sincosf(ang, &sn, &cs);
            s[i0] = make_float2(a.x + b.x, a.y + b.y);
            s[i1] = make_float2(dx * cs - dy * sn, dx * sn + dy * cs);
        }
        __syncthreads();
    }

    // pointwise multiply (both bit-reversed -> aligned)
    #pragma unroll
    for (int t = 0; t < 4; t++) {
        int j = tid + t * 256;
        s[j] = cmul(s[j], g_af[h * N_ + j]);
    }
    __syncthreads();

    // inverse DIT (bit-rev in, natural out, +twiddles; 1/N folded into g_af)
    for (int span = 1; span <= N_ / 2; span <<= 1) {
        #pragma unroll
        for (int t = 0; t < 2; t++) {
            int j = tid + t * 256;
            int pos = j & (span - 1);
            int i0 = ((j & ~(span - 1)) << 1) | pos;
            int i1 = i0 + span;
            float2 a = s[i0], b = s[i1];
            float ang = PI_ * (float)pos / (float)span;
            float sn, cs; __sincosf(ang, &sn, &cs);
            float2 bw = make_float2(b.x * cs - b.y * sn, b.x * sn + b.y * cs);
            s[i0] = make_float2(a.x + bw.x, a.y + bw.y);
            s[i1] = make_float2(a.x - bw.x, a.y - bw.y);
        }
        __syncthreads();
    }

    float* y0 = g_y + ((size_t)h * N_ + 2 * p) * N_;
    #pragma unroll
    for (int t = 0; t < 4; t++) {
        int j = tid + t * 256;
        y0[j]       = s[j].x;
        y0[j + N_]  = s[j].y;
    }
}

// ---------------------------------------------------------------------------
// Transpose + residual: x1[(b<<10)+i][h*64+k] = x[...] + y[h][b*64+k][i]
// 32x32 tiles, both sides coalesced. Also writes fp16 copy x1h.
// ---------------------------------------------------------------------------
__global__ void __launch_bounds__(256) transpose_residual_kernel(
    const float* __restrict__ x)
{
    __shared__ float ts[32][33];
    int h = blockIdx.z / B_, b = blockIdx.z % B_;
    int i0 = blockIdx.x * 32;
    int k0 = blockIdx.y * 32;
    int tx = threadIdx.x & 31, ty = threadIdx.x >> 5;   // ty 0..7

    #pragma unroll
    for (int r = 0; r < 4; r++) {
        int kl = ty + r * 8;
        ts[kl][tx] = g_y[((size_t)h * N_ + b * 64 + k0 + kl) * N_ + i0 + tx];
    }
    __syncthreads();
    #pragma unroll
    for (int r = 0; r < 4; r++) {
        int i = i0 + ty + r * 8;
        size_t o = ((size_t)(b << 10) + i) * D_ + h * 64 + k0 + tx;
        float res = x[o] + ts[tx][ty + r * 8];
        g_x1[o] = res;
        g_x1h[o] = __float2half(res);
    }
}

// ---------------------------------------------------------------------------
// Warp-per-row LayerNorm (no smem, shuffle reduction). 8 rows/block.
// ---------------------------------------------------------------------------
__device__ __forceinline__ void warp_stats(const float4* v, float& mu, float& inv) {
    float s = 0.f, q = 0.f;
    #pragma unroll
    for (int i = 0; i < 6; i++) {
        s += v[i].x + v[i].y + v[i].z + v[i].w;
        q += v[i].x*v[i].x + v[i].y*v[i].y + v[i].z*v[i].z + v[i].w*v[i].w;
    }
    #pragma unroll
    for (int o = 16; o; o >>= 1) {
        s += __shfl_xor_sync(0xffffffffu, s, o);
        q += __shfl_xor_sync(0xffffffffu, q, o);
    }
    mu = s * (1.f / D_);
    float var = q * (1.f / D_) - mu * mu;
    inv = rsqrtf(var + EPS_);
}

__global__ void __launch_bounds__(256) ln1_kernel(
    const float* __restrict__ in, const float* __restrict__ scale,
    const float* __restrict__ bias)
{
    int warp = threadIdx.x >> 5, lane = threadIdx.x & 31;
    size_t row = (size_t)blockIdx.x * 8 + warp;
    const float4* p = reinterpret_cast<const float4*>(in + row * D_);
    const float4* sc = reinterpret_cast<const float4*>(scale);
    const float4* bi = reinterpret_cast<const float4*>(bias);
    float4 v[6];
    #pragma unroll
    for (int i = 0; i < 6; i++) v[i] = p[lane + 32 * i];
    float mu, inv;
    warp_stats(v, mu, inv);
    #pragma unroll
    for (int i = 0; i < 6; i++) {
        int g4 = lane + 32 * i;
        float4 s4 = sc[g4], b4 = bi[g4];
        __half2 h0 = __floats2half2_rn((v[i].x - mu) * inv * s4.x + b4.x,
                                       (v[i].y - mu) * inv * s4.y + b4.y);
        __half2 h1 = __floats2half2_rn((v[i].z - mu) * inv * s4.z + b4.z,
                                       (v[i].w - mu) * inv * s4.w + b4.w);
        uint2 u; u.x = *(uint32_t*)&h0; u.y = *(uint32_t*)&h1;
        *reinterpret_cast<uint2*>(g_xn + row * D_ + g4 * 4) = u;
    }
}

// input t is fp16. LAST=0: z = swish(LN(t)) -> g_zh
//                  LAST=1: out = log_cosh(swish(LN(t)) + x1)
template<int LAST>
__global__ void __launch_bounds__(256) ln_swish_kernel(
    const float* __restrict__ scale, const float* __restrict__ bias,
    float* __restrict__ out)
{
    int warp = threadIdx.x >> 5, lane = threadIdx.x & 31;
    size_t row = (size_t)blockIdx.x * 8 + warp;
    const uint2* p = reinterpret_cast<const uint2*>(g_th + row * D_);
    const float4* sc = reinterpret_cast<const float4*>(scale);
    const float4* bi = reinterpret_cast<const float4*>(bias);
    float4 v[6];
    #pragma unroll
    for (int i = 0; i < 6; i++) {
        uint2 u = p[lane + 32 * i];
        __half2 h0 = *(__half2*)&u.x, h1 = *(__half2*)&u.y;
        float2 f0 = __half22float2(h0), f1 = __half22float2(h1);
        v[i] = make_float4(f0.x, f0.y, f1.x, f1.y);
    }
    float mu, inv;
    warp_stats(v, mu, inv);
    #pragma unroll
    for (int i = 0; i < 6; i++) {
        int g4 = lane + 32 * i;
        float4 s4 = sc[g4], b4 = bi[g4];
        float r[4] = {(v[i].x - mu) * inv * s4.x + b4.x,
                      (v[i].y - mu) * inv * s4.y + b4.y,
                      (v[i].z - mu) * inv * s4.z + b4.z,
                      (v[i].w - mu) * inv * s4.w + b4.w};
        #pragma unroll
        for (int c = 0; c < 4; c++) r[c] = r[c] * (1.f / (1.f + expf(-r[c])));
        if (LAST) {
            float4 xr = *reinterpret_cast<const float4*>(g_x1 + row * D_ + g4 * 4);
            float xs[4] = {xr.x, xr.y, xr.z, xr.w};
            float4 o4;
            float* po = &o4.x;
            #pragma unroll
            for (int c = 0; c < 4; c++) {
                float sum = r[c] + xs[c];
                float ax = fabsf(sum);
                po[c] = ax + log1pf(expf(-2.f * ax)) - 0.69314718055994530942f;
            }
            *reinterpret_cast<float4*>(out + row * D_ + g4 * 4) = o4;
        } else {
            __half2 h0 = __floats2half2_rn(r[0], r[1]);
            __half2 h1 = __floats2half2_rn(r[2], r[3]);
            uint2 u; u.x = *(uint32_t*)&h0; u.y = *(uint32_t*)&h1;
            *reinterpret_cast<uint2*>(g_zh + row * D_ + g4 * 4) = u;
        }
    }
}

// ---------------------------------------------------------------------------
// HMMA fp16 GEMM (fp32 accum). Block 128x128, BK=32, 3-stage cp.async,
// 2 CTAs/SM. 8 warps (2m x 4n), warp tile 64x32, m16n8k16.
// MODE 0: GEMM1 -> smem transpose (64-col chunks), scatter v [h][b*64+k][j]
// MODE 2: FFN   -> t = D + bias (fp16)
// ---------------------------------------------------------------------------
#define BM 128
#define BN 128
#define TILE_B   8192u            // 128x32 fp16
#define STAGE_B  (2u*TILE_B)      // A, B
#define NSTAGE   3
#define SMEM_BYTES (NSTAGE*STAGE_B)   // 49152 ; epi buffer 33280 fits

// 64B-row swizzle: 4 chunks of 16B; chunk' = cc ^ ((row>>1)&3)
__device__ __forceinline__ uint32_t sw_off(int row, int cc) {
    return (uint32_t)(row * 64 + ((cc ^ ((row >> 1) & 3)) << 4));
}

__device__ __forceinline__ void cp_tile(uint32_t dstBase, const __half* src,
                                        int rowBase, int kBase, int ld, int tid)
{
    const char* g = (const char*)src + ((size_t)rowBase * ld + kBase) * 2;
    #pragma unroll
    for (int t = 0; t < 2; t++) {
        int ci = tid + t * 256;
        int row = ci >> 2, cc = ci & 3;
        CP_ASYNC(dstBase + sw_off(row, cc), g + (size_t)row * ld * 2 + cc * 16);
    }
}

template<int MODE>
__global__ void __launch_bounds__(256, 2) tc_gemm(
    const __half* __restrict__ A, const __half* __restrict__ Bm,
    int Kdim,
    __half* __restrict__ out_h,               // mode0: vc, mode2: t
    const float* __restrict__ bias)           // mode2
{
    extern __shared__ char smem[];
    const int tid = threadIdx.x;
    const int wid = tid >> 5, lane = tid & 31;
    const uint32_t sbase = smem_u32(smem);

    const int mBase = blockIdx.y * BM;
    const int nBase = blockIdx.x * BN;

    const int warpM = wid >> 2;     // 0..1 (x64 rows)
    const int warpN = wid & 3;      // 0..3 (x32 cols)

    const int nc = Kdim >> 5;       // BK = 32

    #pragma unroll
    for (int s = 0; s < NSTAGE - 1; s++) {
        uint32_t sb = sbase + s * STAGE_B;
        cp_tile(sb,          A,  mBase, s * 32, Kdim, tid);
        cp_tile(sb + TILE_B, Bm, nBase, s * 32, Kdim, tid);
        CP_COMMIT();
    }

    float acc[4][4][4] = {};
    const int lrow = lane & 15;
    const int lsel = lane >> 4;

    for (int c = 0; c < nc; c++) {
        CP_WAIT(NSTAGE - 2);
        __syncthreads();

        int pre = c + NSTAGE - 1;
        if (pre < nc) {
            uint32_t sb = sbase + (pre % NSTAGE) * STAGE_B;
            cp_tile(sb,          A,  mBase, pre * 32, Kdim, tid);
            cp_tile(sb + TILE_B, Bm, nBase, pre * 32, Kdim, tid);
            CP_COMMIT();
        }

        uint32_t stA = sbase + (c % NSTAGE) * STAGE_B;
        uint32_t stB = stA + TILE_B;

        #pragma unroll
        for (int kk = 0; kk < 2; kk++) {
            int cc = kk * 2 + lsel;
            uint32_t aF[4][4], bF[2][4];
            #pragma unroll
            for (int mt = 0; mt < 4; mt++) {
                int r = warpM * 64 + mt * 16 + lrow;
                ldsm_x4(aF[mt], stA + sw_off(r, cc));
            }
            #pragma unroll
            for (int nt2 = 0; nt2 < 2; nt2++) {
                int r = warpN * 32 + nt2 * 16 + lrow;
                ldsm_x4(bF[nt2], stB + sw_off(r, cc));
            }
            #pragma unroll
            for (int mt = 0; mt < 4; mt++)
                #pragma unroll
                for (int nt = 0; nt < 4; nt++) {
                    uint32_t b0 = bF[nt >> 1][nt & 1];
                    uint32_t b1 = bF[nt >> 1][(nt & 1) + 2];
                    mma16816(acc[mt][nt], aF[mt], b0, b1);
                }
        }
    }
    CP_WAIT(0);

    const int mBaseW = mBase + warpM * 64;
    const int nBaseW = nBase + warpN * 32;

    if (MODE == 0) {
        // two 64-col chunks through smem [128][65], then column writes
        float* sbuf = reinterpret_cast<float*>(smem);
        const int LDS = 65;
        #pragma unroll
        for (int hf = 0; hf < 2; hf++) {
            __syncthreads();
            if ((warpN >> 1) == hf) {
                #pragma unroll
                for (int mt = 0; mt < 4; mt++)
                    #pragma unroll
                    for (int nt = 0; nt < 4; nt++) {
                        int rl = warpM * 64 + mt * 16 + (lane >> 2);
                        int cl = (warpN & 1) * 32 + nt * 8 + ((lane & 3) << 1);
                        sbuf[rl * LDS + cl]           = acc[mt][nt][0];
                        sbuf[rl * LDS + cl + 1]       = acc[mt][nt][1];
                        sbuf[(rl + 8) * LDS + cl]     = acc[mt][nt][2];
                        sbuf[(rl + 8) * LDS + cl + 1] = acc[mt][nt][3];
                    }
            }
            __syncthreads();
            #pragma unroll
            for (int i = 0; i < 8; i++) {
                int cl = wid * 8 + i;
                int cg = nBase + hf * 64 + cl;
                int h = cg >> 6, k = cg & 63;
                #pragma unroll
                for (int q = 0; q < 2; q++) {
                    int m = q * 64 + lane * 2;
                    int mg = mBase + m;
                    int b = mg >> 10, j = mg & 1023;
                    size_t o = (((size_t)(h << 10) + (b << 6) + k) << 10) + j;
                    __half2 hv = __floats2half2_rn(sbuf[m * LDS + cl],
                                                   sbuf[(m + 1) * LDS + cl]);
                    *reinterpret_cast<__half2*>(out_h + o) = hv;
                }
            }
        }
    } else {
        #pragma unroll
        for (int mt = 0; mt < 4; mt++)
            #pragma unroll
            for (int nt = 0; nt < 4; nt++) {
                int i0 = mBaseW + mt * 16 + (lane >> 2);
                int cl = nBaseW + nt * 8 + ((lane & 3) << 1);
                #pragma unroll
                for (int h2 = 0; h2 < 2; h2++) {
                    int i = i0 + h2 * 8;
                    float v0 = acc[mt][nt][h2 * 2];
                    float v1 = acc[mt][nt][h2 * 2 + 1];
                    size_t o = (size_t)i * D_ + cl;
                    *reinterpret_cast<__half2*>(out_h + o) =
                        __floats2half2_rn(v0 + bias[cl], v1 + bias[cl + 1]);
                }
            }
    }
}

// ---------------------------------------------------------------------------
// Launch (prep kernels forked onto a second captured stream)
// ---------------------------------------------------------------------------
extern "C" void kernel_launch(void* const* d_in, const int* in_sizes, int n_in,
                              void* d_out, int out_size)
{
    const float* x     = (const float*)d_in[0];
    const float* ln1_s = (const float*)d_in[1];
    const float* ln1_b = (const float*)d_in[2];
    const float* Wv    = (const float*)d_in[3];
    const float* alpha = (const float*)d_in[4];
    const float* Wf    = (const float*)d_in[5];
    const float* bf    = (const float*)d_in[6];
    const float* lnf_s = (const float*)d_in[7];
    const float* lnf_b = (const float*)d_in[8];
    float* out = (float*)d_out;

    static cudaStream_t s2 = nullptr;
    static cudaEvent_t ev0 = nullptr, evWv = nullptr, evAf = nullptr, evWf = nullptr;
    if (!s2) {
        cudaStreamCreateWithFlags(&s2, cudaStreamNonBlocking);
        cudaEventCreateWithFlags(&ev0,  cudaEventDisableTiming);
        cudaEventCreateWithFlags(&evWv, cudaEventDisableTiming);
        cudaEventCreateWithFlags(&evAf, cudaEventDisableTiming);
        cudaEventCreateWithFlags(&evWf, cudaEventDisableTiming);
        cudaFuncSetAttribute(tc_gemm<0>, cudaFuncAttributeMaxDynamicSharedMemorySize, SMEM_BYTES);
        cudaFuncSetAttribute(tc_gemm<2>, cudaFuncAttributeMaxDynamicSharedMemorySize, SMEM_BYTES);
    }

    __half *xn, *wvT, *wfT, *vc, *x1h, *th, *zh;
    cudaGetSymbolAddress((void**)&xn, g_xn);
    cudaGetSymbolAddress((void**)&wvT, g_wvT);
    cudaGetSymbolAddress((void**)&wfT, g_wfT);
    cudaGetSymbolAddress((void**)&vc, g_vc);
    cudaGetSymbolAddress((void**)&x1h, g_x1h);
    cudaGetSymbolAddress((void**)&th, g_th);
    cudaGetSymbolAddress((void**)&zh, g_zh);

    // fork: prep kernels on s2
    cudaEventRecord(ev0, 0);
    cudaStreamWaitEvent(s2, ev0, 0);
    conv_wvT_kernel<<<(D_*D_ + 255)/256, 256, 0, s2>>>(Wv);
    cudaEventRecord(evWv, s2);
    fft_alpha_kernel<<<H_, 256, 0, s2>>>(alpha);
    cudaEventRecord(evAf, s2);
    conv_wfT_kernel<<<(L_*D_*D_ + 255)/256, 256, 0, s2>>>(Wf);
    cudaEventRecord(evWf, s2);

    // main stream
    ln1_kernel<<<M_/8, 256>>>(x, ln1_s, ln1_b);

    cudaStreamWaitEvent(0, evWv, 0);
    tc_gemm<0><<<dim3(D_/BN, M_/BM, 1), 256, SMEM_BYTES>>>(xn, wvT, D_, vc, nullptr);

    // circulant mixing via FFT convolution
    cudaStreamWaitEvent(0, evAf, 0);
    fft_conv_kernel<<<H_ * 512, 256>>>();
    transpose_residual_kernel<<<dim3(32, 2, H_ * B_), 256>>>(x);

    cudaStreamWaitEvent(0, evWf, 0);
    tc_gemm<2><<<dim3(D_/BN, M_/BM, 1), 256, SMEM_BYTES>>>(x1h, wfT, D_, th, bf);
    ln_swish_kernel<0><<<M_/8, 256>>>(lnf_s, lnf_b, nullptr);

    tc_gemm<2><<<dim3(D_/BN, M_/BM, 1), 256, SMEM_BYTES>>>(
        zh, wfT + (size_t)D_*D_, D_, th, bf + D_);
    ln_swish_kernel<1><<<M_/8, 256>>>(lnf_s + D_, lnf_b + D_, out);
}

// round 12
// speedup vs baseline: 1.0048x; 1.0048x over previous
#include <cuda_runtime.h>
#include <cuda_fp16.h>
#include <cstdint>

// ---------------------------------------------------------------------------
// Problem shape
// ---------------------------------------------------------------------------
#define B_  16
#define N_  1024
#define D_  768
#define H_  12
#define HS_ 64
#define M_  (B_*N_)     // 16384 token rows
#define L_  2
#define EPS_ 1e-6f
#define PI_ 3.14159265358979f

// ---------------------------------------------------------------------------
// Scratch
// ---------------------------------------------------------------------------
__device__ __half  g_xn [M_*D_];       // LN1(x)           (GEMM1 A)
__device__ __half  g_wvT[D_*D_];       // Wv^T [n=h*64+k][d]
__device__ __half  g_wfT[L_*D_*D_];    // Wf^T [l][n][d]
__device__ __half  g_vc [H_*N_*N_];    // v [h][b*64+k][j] (FFT input signals)
__device__ float2  g_af [H_*N_];       // FFT4(alpha_h)/N, digit-reversed bins
__device__ float2  g_tw [N_];          // e^{-2*pi*i*k/N}
__device__ __half  g_yh [H_*N_*N_];    // conv result [h][b*64+k][i] (fp16)
__device__ float   g_x1 [M_*D_];       // residual x + y (fp32)
__device__ __half  g_x1h[M_*D_];       // fp16 copy        (FFN1 A)
__device__ __half  g_th [M_*D_];       // ffn gemm out (fp16)
__device__ __half  g_zh [M_*D_];       // swish(ln(t))     (FFN2 A)

// ---------------------------------------------------------------------------
// Helpers
// ---------------------------------------------------------------------------
__device__ __forceinline__ uint32_t smem_u32(const void* p) {
    uint32_t a;
    asm("{ .reg .u64 t; cvta.to.shared.u64 t, %1; cvt.u32.u64 %0, t; }"
        : "=r"(a) : "l"(p));
    return a;
}
__device__ __forceinline__ void ldsm_x4(uint32_t* d, uint32_t addr) {
    asm volatile("ldmatrix.sync.aligned.m8n8.x4.shared.b16 {%0,%1,%2,%3}, [%4];"
                 : "=r"(d[0]), "=r"(d[1]), "=r"(d[2]), "=r"(d[3]) : "r"(addr));
}
__device__ __forceinline__ void mma16816(float* d, const uint32_t* a,
                                         uint32_t b0, uint32_t b1) {
    asm volatile(
        "mma.sync.aligned.m16n8k16.row.col.f32.f16.f16.f32 "
        "{%0,%1,%2,%3}, {%4,%5,%6,%7}, {%8,%9}, {%0,%1,%2,%3};"
        : "+f"(d[0]), "+f"(d[1]), "+f"(d[2]), "+f"(d[3])
        : "r"(a[0]), "r"(a[1]), "r"(a[2]), "r"(a[3]), "r"(b0), "r"(b1));
}
__device__ __forceinline__ float2 cmul(float2 a, float2 b) {
    return make_float2(a.x*b.x - a.y*b.y, a.x*b.y + a.y*b.x);
}
__device__ __forceinline__ float2 cadd(float2 a, float2 b) {
    return make_float2(a.x + b.x, a.y + b.y);
}
__device__ __forceinline__ float2 csub(float2 a, float2 b) {
    return make_float2(a.x - b.x, a.y - b.y);
}
#define CP_ASYNC(dst, src) \
    asm volatile("cp.async.cg.shared.global [%0], [%1], 16;" :: "r"(dst), "l"(src))
#define CP_COMMIT() asm volatile("cp.async.commit_group;" ::: "memory")
#define CP_WAIT(n)  asm volatile("cp.async.wait_group %0;" :: "n"(n) : "memory")

// ---------------------------------------------------------------------------
// Conversion kernels
// ---------------------------------------------------------------------------
__global__ void conv_wvT_kernel(const float* __restrict__ Wv) {
    int idx = blockIdx.x * blockDim.x + threadIdx.x;
    if (idx >= D_ * D_) return;
    int n = idx / D_, d = idx % D_;
    int h = n >> 6, k = n & 63;
    g_wvT[idx] = __float2half(Wv[((size_t)h * D_ + d) * HS_ + k]);
}
__global__ void conv_wfT_kernel(const float* __restrict__ Wf) {
    int idx = blockIdx.x * blockDim.x + threadIdx.x;
    if (idx >= L_ * D_ * D_) return;
    int l = idx / (D_ * D_);
    int r = idx % (D_ * D_);
    int n = r / D_, d = r % D_;
    g_wfT[idx] = __float2half(Wf[(size_t)l * D_ * D_ + (size_t)d * D_ + n]);
}
__global__ void twiddle_kernel() {
    int k = blockIdx.x * 256 + threadIdx.x;
    float ang = -2.f * PI_ * (float)k / (float)N_;
    float sn, cs;
    __sincosf(ang, &sn, &cs);
    g_tw[k] = make_float2(cs, sn);
}

// ---------------------------------------------------------------------------
// Radix-4 FFT building blocks (smem data s[1024], smem twiddle tw[1024]).
// Forward DIF: spans 256,64,16,4,1 -> base-4-digit-reversed output.
// Inverse DIT: spans 1,4,16,64,256, conj twiddles on inputs -> natural order.
// ---------------------------------------------------------------------------
__device__ __forceinline__ void fft4_forward(float2* s, const float2* tw, int tid) {
    #pragma unroll
    for (int st = 0; st < 5; st++) {
        int span = 256 >> (2 * st);
        int pos = tid & (span - 1);
        int g = tid >> (8 - 2 * st);
        int i0 = g * 4 * span + pos;
        int tb = pos << (2 * st);
        float2 a0 = s[i0], a1 = s[i0 + span], a2 = s[i0 + 2*span], a3 = s[i0 + 3*span];
        float2 t0 = cadd(a0, a2), t1 = csub(a0, a2);
        float2 t2 = cadd(a1, a3);
        float2 tr = csub(a1, a3);
        float2 t3 = make_float2(tr.y, -tr.x);          // * (-i)
        float2 w1 = tw[tb], w2 = tw[2*tb], w3 = tw[3*tb];
        s[i0]          = cadd(t0, t2);
        s[i0 + span]   = cmul(cadd(t1, t3), w1);
        s[i0 + 2*span] = cmul(csub(t0, t2), w2);
        s[i0 + 3*span] = cmul(csub(t1, t3), w3);
        __syncthreads();
    }
}
__device__ __forceinline__ void fft4_inverse(float2* s, const float2* tw, int tid) {
    #pragma unroll
    for (int st = 0; st < 5; st++) {
        int span = 1 << (2 * st);
        int pos = tid & (span - 1);
        int g = tid >> (2 * st);
        int i0 = g * 4 * span + pos;
        int tb = pos << (8 - 2 * st);
        float2 w1 = tw[tb], w2 = tw[2*tb], w3 = tw[3*tb];
        // conjugate twiddles on inputs
        float2 b0 = s[i0];
        float2 c1 = s[i0 + span],   b1 = make_float2(c1.x*w1.x + c1.y*w1.y, c1.y*w1.x - c1.x*w1.y);
        float2 c2 = s[i0 + 2*span], b2 = make_float2(c2.x*w2.x + c2.y*w2.y, c2.y*w2.x - c2.x*w2.y);
        float2 c3 = s[i0 + 3*span], b3 = make_float2(c3.x*w3.x + c3.y*w3.y, c3.y*w3.x - c3.x*w3.y);
        float2 t0 = cadd(b0, b2), t1 = csub(b0, b2);
        float2 t2 = cadd(b1, b3);
        float2 tr = csub(b1, b3);
        float2 t3 = make_float2(-tr.y, tr.x);          // * (+i)
        s[i0]          = cadd(t0, t2);
        s[i0 + span]   = cadd(t1, t3);
        s[i0 + 2*span] = csub(t0, t2);
        s[i0 + 3*span] = csub(t1, t3);
        __syncthreads();
    }
}

// ---------------------------------------------------------------------------
// FFT of alpha (radix-4 forward DIF, digit-reversed output, pre-scaled 1/N)
// ---------------------------------------------------------------------------
__global__ void __launch_bounds__(256) fft_alpha_kernel(const float* __restrict__ alpha) {
    __shared__ float2 s[N_];
    __shared__ float2 tw[N_];
    int h = blockIdx.x, tid = threadIdx.x;
    #pragma unroll
    for (int t = 0; t < 4; t++) {
        int j = tid + t * 256;
        tw[j] = g_tw[j];
        s[j] = make_float2(alpha[h * N_ + j] * (1.f / N_), 0.f);
    }
    __syncthreads();
    fft4_forward(s, tw, tid);
    #pragma unroll
    for (int t = 0; t < 4; t++) {
        int j = tid + t * 256;
        g_af[h * N_ + j] = s[j];
    }
}

// ---------------------------------------------------------------------------
// FFT convolution: two real v-rows packed as one complex signal (two-for-one).
// ---------------------------------------------------------------------------
__global__ void __launch_bounds__(256) fft_conv_kernel() {
    __shared__ float2 s[N_];
    __shared__ float2 tw[N_];
    int h = blockIdx.x >> 9;           // /512
    int p = blockIdx.x & 511;
    int tid = threadIdx.x;

    const __half* vr = g_vc + ((size_t)h * N_ + 2 * p) * N_;
    #pragma unroll
    for (int t = 0; t < 4; t++) {
        int j = tid + t * 256;
        tw[j] = g_tw[j];
        s[j] = make_float2(__half2float(vr[j]), __half2float(vr[j + N_]));
    }
    __syncthreads();

    fft4_forward(s, tw, tid);

    // pointwise multiply (both digit-reversed -> aligned)
    #pragma unroll
    for (int t = 0; t < 4; t++) {
        int j = tid + t * 256;
        s[j] = cmul(s[j], g_af[h * N_ + j]);
    }
    __syncthreads();

    fft4_inverse(s, tw, tid);

    __half* y0 = g_yh + ((size_t)h * N_ + 2 * p) * N_;
    #pragma unroll
    for (int t = 0; t < 4; t++) {
        int j = tid + t * 256;
        y0[j]      = __float2half(s[j].x);
        y0[j + N_] = __float2half(s[j].y);
    }
}

// ---------------------------------------------------------------------------
// Transpose + residual: x1[(b<<10)+i][h*64+k] = x[...] + y[h][b*64+k][i]
// ---------------------------------------------------------------------------
__global__ void __launch_bounds__(256) transpose_residual_kernel(
    const float* __restrict__ x)
{
    __shared__ float ts[32][33];
    int h = blockIdx.z / B_, b = blockIdx.z % B_;
    int i0 = blockIdx.x * 32;
    int k0 = blockIdx.y * 32;
    int tx = threadIdx.x & 31, ty = threadIdx.x >> 5;   // ty 0..7

    #pragma unroll
    for (int r = 0; r < 4; r++) {
        int kl = ty + r * 8;
        ts[kl][tx] = __half2float(
            g_yh[((size_t)h * N_ + b * 64 + k0 + kl) * N_ + i0 + tx]);
    }
    __syncthreads();
    #pragma unroll
    for (int r = 0; r < 4; r++) {
        int i = i0 + ty + r * 8;
        size_t o = ((size_t)(b << 10) + i) * D_ + h * 64 + k0 + tx;
        float res = x[o] + ts[tx][ty + r * 8];
        g_x1[o] = res;
        g_x1h[o] = __float2half(res);
    }
}

// ---------------------------------------------------------------------------
// Warp-per-row LayerNorm (no smem, shuffle reduction). 8 rows/block.
// ---------------------------------------------------------------------------
__device__ __forceinline__ void warp_stats(const float4* v, float& mu, float& inv) {
    float s = 0.f, q = 0.f;
    #pragma unroll
    for (int i = 0; i < 6; i++) {
        s += v[i].x + v[i].y + v[i].z + v[i].w;
        q += v[i].x*v[i].x + v[i].y*v[i].y + v[i].z*v[i].z + v[i].w*v[i].w;
    }
    #pragma unroll
    for (int o = 16; o; o >>= 1) {
        s += __shfl_xor_sync(0xffffffffu, s, o);
        q += __shfl_xor_sync(0xffffffffu, q, o);
    }
    mu = s * (1.f / D_);
    float var = q * (1.f / D_) - mu * mu;
    inv = rsqrtf(var + EPS_);
}

__global__ void __launch_bounds__(256) ln1_kernel(
    const float* __restrict__ in, const float* __restrict__ scale,
    const float* __restrict__ bias)
{
    int warp = threadIdx.x >> 5, lane = threadIdx.x & 31;
    size_t row = (size_t)blockIdx.x * 8 + warp;
    const float4* p = reinterpret_cast<const float4*>(in + row * D_);
    const float4* sc = reinterpret_cast<const float4*>(scale);
    const float4* bi = reinterpret_cast<const float4*>(bias);
    float4 v[6];
    #pragma unroll
    for (int i = 0; i < 6; i++) v[i] = p[lane + 32 * i];
    float mu, inv;
    warp_stats(v, mu, inv);
    #pragma unroll
    for (int i = 0; i < 6; i++) {
        int g4 = lane + 32 * i;
        float4 s4 = sc[g4], b4 = bi[g4];
        __half2 h0 = __floats2half2_rn((v[i].x - mu) * inv * s4.x + b4.x,
                                       (v[i].y - mu) * inv * s4.y + b4.y);
        __half2 h1 = __floats2half2_rn((v[i].z - mu) * inv * s4.z + b4.z,
                                       (v[i].w - mu) * inv * s4.w + b4.w);
        uint2 u; u.x = *(uint32_t*)&h0; u.y = *(uint32_t*)&h1;
        *reinterpret_cast<uint2*>(g_xn + row * D_ + g4 * 4) = u;
    }
}

// input t is fp16. LAST=0: z = swish(LN(t)) -> g_zh
//                  LAST=1: out = log_cosh(swish(LN(t)) + x1)
template<int LAST>
__global__ void __launch_bounds__(256) ln_swish_kernel(
    const float* __restrict__ scale, const float* __restrict__ bias,
    float* __restrict__ out)
{
    int warp = threadIdx.x >> 5, lane = threadIdx.x & 31;
    size_t row = (size_t)blockIdx.x * 8 + warp;
    const uint2* p = reinterpret_cast<const uint2*>(g_th + row * D_);
    const float4* sc = reinterpret_cast<const float4*>(scale);
    const float4* bi = reinterpret_cast<const float4*>(bias);
    float4 v[6];
    #pragma unroll
    for (int i = 0; i < 6; i++) {
        uint2 u = p[lane + 32 * i];
        __half2 h0 = *(__half2*)&u.x, h1 = *(__half2*)&u.y;
        float2 f0 = __half22float2(h0), f1 = __half22float2(h1);
        v[i] = make_float4(f0.x, f0.y, f1.x, f1.y);
    }
    float mu, inv;
    warp_stats(v, mu, inv);
    #pragma unroll
    for (int i = 0; i < 6; i++) {
        int g4 = lane + 32 * i;
        float4 s4 = sc[g4], b4 = bi[g4];
        float r[4] = {(v[i].x - mu) * inv * s4.x + b4.x,
                      (v[i].y - mu) * inv * s4.y + b4.y,
                      (v[i].z - mu) * inv * s4.z + b4.z,
                      (v[i].w - mu) * inv * s4.w + b4.w};
        #pragma unroll
        for (int c = 0; c < 4; c++) r[c] = r[c] * (1.f / (1.f + expf(-r[c])));
        if (LAST) {
            float4 xr = *reinterpret_cast<const float4*>(g_x1 + row * D_ + g4 * 4);
            float xs[4] = {xr.x, xr.y, xr.z, xr.w};
            float4 o4;
            float* po = &o4.x;
            #pragma unroll
            for (int c = 0; c < 4; c++) {
                float sum = r[c] + xs[c];
                float ax = fabsf(sum);
                po[c] = ax + log1pf(expf(-2.f * ax)) - 0.69314718055994530942f;
            }
            *reinterpret_cast<float4*>(out + row * D_ + g4 * 4) = o4;
        } else {
            __half2 h0 = __floats2half2_rn(r[0], r[1]);
            __half2 h1 = __floats2half2_rn(r[2], r[3]);
            uint2 u; u.x = *(uint32_t*)&h0; u.y = *(uint32_t*)&h1;
            *reinterpret_cast<uint2*>(g_zh + row * D_ + g4 * 4) = u;
        }
    }
}

// ---------------------------------------------------------------------------
// HMMA fp16 GEMM (fp32 accum). Block 128x128, BK=32, 3-stage cp.async,
// 2 CTAs/SM. 8 warps (2m x 4n), warp tile 64x32, m16n8k16.
// MODE 0: GEMM1 -> smem transpose (64-col chunks), scatter v [h][b*64+k][j]
// MODE 2: FFN   -> t = D + bias (fp16)
// ---------------------------------------------------------------------------
#define BM 128
#define BN 128
#define TILE_B   8192u            // 128x32 fp16
#define STAGE_B  (2u*TILE_B)      // A, B
#define NSTAGE   3
#define SMEM_BYTES (NSTAGE*STAGE_B)   // 49152 ; epi buffer 33280 fits

// 64B-row swizzle: 4 chunks of 16B; chunk' = cc ^ ((row>>1)&3)
__device__ __forceinline__ uint32_t sw_off(int row, int cc) {
    return (uint32_t)(row * 64 + ((cc ^ ((row >> 1) & 3)) << 4));
}

__device__ __forceinline__ void cp_tile(uint32_t dstBase, const __half* src,
                                        int rowBase, int kBase, int ld, int tid)
{
    const char* g = (const char*)src + ((size_t)rowBase * ld + kBase) * 2;
    #pragma unroll
    for (int t = 0; t < 2; t++) {
        int ci = tid + t * 256;
        int row = ci >> 2, cc = ci & 3;
        CP_ASYNC(dstBase + sw_off(row, cc), g + (size_t)row * ld * 2 + cc * 16);
    }
}

template<int MODE>
__global__ void __launch_bounds__(256, 2) tc_gemm(
    const __half* __restrict__ A, const __half* __restrict__ Bm,
    int Kdim,
    __half* __restrict__ out_h,               // mode0: vc, mode2: t
    const float* __restrict__ bias)           // mode2
{
    extern __shared__ char smem[];
    const int tid = threadIdx.x;
    const int wid = tid >> 5, lane = tid & 31;
    const uint32_t sbase = smem_u32(smem);

    const int mBase = blockIdx.y * BM;
    const int nBase = blockIdx.x * BN;

    const int warpM = wid >> 2;     // 0..1 (x64 rows)
    const int warpN = wid & 3;      // 0..3 (x32 cols)

    const int nc = Kdim >> 5;       // BK = 32

    #pragma unroll
    for (int s = 0; s < NSTAGE - 1; s++) {
        uint32_t sb = sbase + s * STAGE_B;
        cp_tile(sb,          A,  mBase, s * 32, Kdim, tid);
        cp_tile(sb + TILE_B, Bm, nBase, s * 32, Kdim, tid);
        CP_COMMIT();
    }

    float acc[4][4][4] = {};
    const int lrow = lane & 15;
    const int lsel = lane >> 4;

    for (int c = 0; c < nc; c++) {
        CP_WAIT(NSTAGE - 2);
        __syncthreads();

        int pre = c + NSTAGE - 1;
        if (pre < nc) {
            uint32_t sb = sbase + (pre % NSTAGE) * STAGE_B;
            cp_tile(sb,          A,  mBase, pre * 32, Kdim, tid);
            cp_tile(sb + TILE_B, Bm, nBase, pre * 32, Kdim, tid);
            CP_COMMIT();
        }

        uint32_t stA = sbase + (c % NSTAGE) * STAGE_B;
        uint32_t stB = stA + TILE_B;

        #pragma unroll
        for (int kk = 0; kk < 2; kk++) {
            int cc = kk * 2 + lsel;
            uint32_t aF[4][4], bF[2][4];
            #pragma unroll
            for (int mt = 0; mt < 4; mt++) {
                int r = warpM * 64 + mt * 16 + lrow;
                ldsm_x4(aF[mt], stA + sw_off(r, cc));
            }
            #pragma unroll
            for (int nt2 = 0; nt2 < 2; nt2++) {
                int r = warpN * 32 + nt2 * 16 + lrow;
                ldsm_x4(bF[nt2], stB + sw_off(r, cc));
            }
            #pragma unroll
            for (int mt = 0; mt < 4; mt++)
                #pragma unroll
                for (int nt = 0; nt < 4; nt++) {
                    uint32_t b0 = bF[nt >> 1][nt & 1];
                    uint32_t b1 = bF[nt >> 1][(nt & 1) + 2];
                    mma16816(acc[mt][nt], aF[mt], b0, b1);
                }
        }
    }
    CP_WAIT(0);

    const int mBaseW = mBase + warpM * 64;
    const int nBaseW = nBase + warpN * 32;

    if (MODE == 0) {
        // two 64-col chunks through smem [128][65], then column writes
        float* sbuf = reinterpret_cast<float*>(smem);
        const int LDS = 65;
        #pragma unroll
        for (int hf = 0; hf < 2; hf++) {
            __syncthreads();
            if ((warpN >> 1) == hf) {
                #pragma unroll
                for (int mt = 0; mt < 4; mt++)
                    #pragma unroll
                    for (int nt = 0; nt < 4; nt++) {
                        int rl = warpM * 64 + mt * 16 + (lane >> 2);
                        int cl = (warpN & 1) * 32 + nt * 8 + ((lane & 3) << 1);
                        sbuf[rl * LDS + cl]           = acc[mt][nt][0];
                        sbuf[rl * LDS + cl + 1]       = acc[mt][nt][1];
                        sbuf[(rl + 8) * LDS + cl]     = acc[mt][nt][2];
                        sbuf[(rl + 8) * LDS + cl + 1] = acc[mt][nt][3];
                    }
            }
            __syncthreads();
            #pragma unroll
            for (int i = 0; i < 8; i++) {
                int cl = wid * 8 + i;
                int cg = nBase + hf * 64 + cl;
                int h = cg >> 6, k = cg & 63;
                #pragma unroll
                for (int q = 0; q < 2; q++) {
                    int m = q * 64 + lane * 2;
                    int mg = mBase + m;
                    int b = mg >> 10, j = mg & 1023;
                    size_t o = (((size_t)(h << 10) + (b << 6) + k) << 10) + j;
                    __half2 hv = __floats2half2_rn(sbuf[m * LDS + cl],
                                                   sbuf[(m + 1) * LDS + cl]);
                    *reinterpret_cast<__half2*>(out_h + o) = hv;
                }
            }
        }
    } else {
        #pragma unroll
        for (int mt = 0; mt < 4; mt++)
            #pragma unroll
            for (int nt = 0; nt < 4; nt++) {
                int i0 = mBaseW + mt * 16 + (lane >> 2);
                int cl = nBaseW + nt * 8 + ((lane & 3) << 1);
                #pragma unroll
                for (int h2 = 0; h2 < 2; h2++) {
                    int i = i0 + h2 * 8;
                    float v0 = acc[mt][nt][h2 * 2];
                    float v1 = acc[mt][nt][h2 * 2 + 1];
                    size_t o = (size_t)i * D_ + cl;
                    *reinterpret_cast<__half2*>(out_h + o) =
                        __floats2half2_rn(v0 + bias[cl], v1 + bias[cl + 1]);
                }
            }
    }
}

// ---------------------------------------------------------------------------
// Launch (prep kernels forked onto a second captured stream)
// ---------------------------------------------------------------------------
extern "C" void kernel_launch(void* const* d_in, const int* in_sizes, int n_in,
                              void* d_out, int out_size)
{
    const float* x     = (const float*)d_in[0];
    const float* ln1_s = (const float*)d_in[1];
    const float* ln1_b = (const float*)d_in[2];
    const float* Wv    = (const float*)d_in[3];
    const float* alpha = (const float*)d_in[4];
    const float* Wf    = (const float*)d_in[5];
    const float* bf    = (const float*)d_in[6];
    const float* lnf_s = (const float*)d_in[7];
    const float* lnf_b = (const float*)d_in[8];
    float* out = (float*)d_out;

    static cudaStream_t s2 = nullptr;
    static cudaEvent_t ev0 = nullptr, evWv = nullptr, evAf = nullptr, evWf = nullptr;
    if (!s2) {
        cudaStreamCreateWithFlags(&s2, cudaStreamNonBlocking);
        cudaEventCreateWithFlags(&ev0,  cudaEventDisableTiming);
        cudaEventCreateWithFlags(&evWv, cudaEventDisableTiming);
        cudaEventCreateWithFlags(&evAf, cudaEventDisableTiming);
        cudaEventCreateWithFlags(&evWf, cudaEventDisableTiming);
        cudaFuncSetAttribute(tc_gemm<0>, cudaFuncAttributeMaxDynamicSharedMemorySize, SMEM_BYTES);
        cudaFuncSetAttribute(tc_gemm<2>, cudaFuncAttributeMaxDynamicSharedMemorySize, SMEM_BYTES);
    }

    __half *xn, *wvT, *wfT, *vc, *x1h, *th, *zh;
    cudaGetSymbolAddress((void**)&xn, g_xn);
    cudaGetSymbolAddress((void**)&wvT, g_wvT);
    cudaGetSymbolAddress((void**)&wfT, g_wfT);
    cudaGetSymbolAddress((void**)&vc, g_vc);
    cudaGetSymbolAddress((void**)&x1h, g_x1h);
    cudaGetSymbolAddress((void**)&th, g_th);
    cudaGetSymbolAddress((void**)&zh, g_zh);

    // fork: prep kernels on s2
    cudaEventRecord(ev0, 0);
    cudaStreamWaitEvent(s2, ev0, 0);
    conv_wvT_kernel<<<(D_*D_ + 255)/256, 256, 0, s2>>>(Wv);
    cudaEventRecord(evWv, s2);
    twiddle_kernel<<<4, 256, 0, s2>>>();
    fft_alpha_kernel<<<H_, 256, 0, s2>>>(alpha);
    cudaEventRecord(evAf, s2);
    conv_wfT_kernel<<<(L_*D_*D_ + 255)/256, 256, 0, s2>>>(Wf);
    cudaEventRecord(evWf, s2);

    // main stream
    ln1_kernel<<<M_/8, 256>>>(x, ln1_s, ln1_b);

    cudaStreamWaitEvent(0, evWv, 0);
    tc_gemm<0><<<dim3(D_/BN, M_/BM, 1), 256, SMEM_BYTES>>>(xn, wvT, D_, vc, nullptr);

    // circulant mixing via radix-4 FFT convolution
    cudaStreamWaitEvent(0, evAf, 0);
    fft_conv_kernel<<<H_ * 512, 256>>>();
    transpose_residual_kernel<<<dim3(32, 2, H_ * B_), 256>>>(x);

    cudaStreamWaitEvent(0, evWf, 0);
    tc_gemm<2><<<dim3(D_/BN, M_/BM, 1), 256, SMEM_BYTES>>>(x1h, wfT, D_, th, bf);
    ln_swish_kernel<0><<<M_/8, 256>>>(lnf_s, lnf_b, nullptr);

    tc_gemm<2><<<dim3(D_/BN, M_/BM, 1), 256, SMEM_BYTES>>>(
        zh, wfT + (size_t)D_*D_, D_, th, bf + D_);
    ln_swish_kernel<1><<<M_/8, 256>>>(lnf_s + D_, lnf_b + D_, out);
}

// round 13
// speedup vs baseline: 1.1211x; 1.1158x over previous
#include <cuda_runtime.h>
#include <cuda_fp16.h>
#include <cstdint>

// ---------------------------------------------------------------------------
// Problem shape
// ---------------------------------------------------------------------------
#define B_  16
#define N_  1024
#define D_  768
#define H_  12
#define HS_ 64
#define M_  (B_*N_)     // 16384 token rows
#define L_  2
#define EPS_ 1e-6f

// ---------------------------------------------------------------------------
// Scratch
// ---------------------------------------------------------------------------
__device__ __half g_xn [M_*D_];        // LN1(x)           (GEMM1 A)
__device__ __half g_wvT[D_*D_];        // Wv^T [n=h*64+k][d]
__device__ __half g_wfT[L_*D_*D_];     // Wf^T [l][n][d]
__device__ __half g_vc [H_*N_*N_];     // v [h][b*64+k][j] (circ B)
__device__ __half g_cc [H_*N_*N_];     // C [h][i][j]      (circ A)
__device__ __half g_x1h[M_*D_];        // x + y residual (fp16 only)
__device__ __half g_th [M_*D_];        // ffn gemm out (fp16)
__device__ __half g_zh [M_*D_];        // swish(ln(t))     (FFN2 A)

// ---------------------------------------------------------------------------
// Helpers
// ---------------------------------------------------------------------------
__device__ __forceinline__ uint32_t smem_u32(const void* p) {
    uint32_t a;
    asm("{ .reg .u64 t; cvta.to.shared.u64 t, %1; cvt.u32.u64 %0, t; }"
        : "=r"(a) : "l"(p));
    return a;
}
__device__ __forceinline__ void ldsm_x4(uint32_t* d, uint32_t addr) {
    asm volatile("ldmatrix.sync.aligned.m8n8.x4.shared.b16 {%0,%1,%2,%3}, [%4];"
                 : "=r"(d[0]), "=r"(d[1]), "=r"(d[2]), "=r"(d[3]) : "r"(addr));
}
__device__ __forceinline__ void mma16816(float* d, const uint32_t* a,
                                         uint32_t b0, uint32_t b1) {
    asm volatile(
        "mma.sync.aligned.m16n8k16.row.col.f32.f16.f16.f32 "
        "{%0,%1,%2,%3}, {%4,%5,%6,%7}, {%8,%9}, {%0,%1,%2,%3};"
        : "+f"(d[0]), "+f"(d[1]), "+f"(d[2]), "+f"(d[3])
        : "r"(a[0]), "r"(a[1]), "r"(a[2]), "r"(a[3]), "r"(b0), "r"(b1));
}
#define CP_ASYNC(dst, src) \
    asm volatile("cp.async.cg.shared.global [%0], [%1], 16;" :: "r"(dst), "l"(src))
#define CP_COMMIT() asm volatile("cp.async.commit_group;" ::: "memory")
#define CP_WAIT(n)  asm volatile("cp.async.wait_group %0;" :: "n"(n) : "memory")

// ---------------------------------------------------------------------------
// Weight prep: tiled transposes (both sides coalesced)
// ---------------------------------------------------------------------------
// Wv [H][D][HS] -> wvT [h*64+k][d]. grid (D/32, HS/32, H)
__global__ void __launch_bounds__(256) conv_wvT_kernel(const float* __restrict__ Wv) {
    __shared__ float ts[32][33];
    int d0 = blockIdx.x * 32, k0 = blockIdx.y * 32, h = blockIdx.z;
    int tx = threadIdx.x & 31, ty = threadIdx.x >> 5;
    #pragma unroll
    for (int r = 0; r < 4; r++) {
        int d = d0 + ty + r * 8;
        ts[ty + r * 8][tx] = Wv[((size_t)h * D_ + d) * HS_ + k0 + tx];
    }
    __syncthreads();
    #pragma unroll
    for (int r = 0; r < 4; r++) {
        int k = k0 + ty + r * 8;
        g_wvT[(size_t)(h * HS_ + k) * D_ + d0 + tx] = __float2half(ts[tx][ty + r * 8]);
    }
}
// Wf [L][D][D] -> wfT [l][n][d]. grid (D/32, D/32, L)
__global__ void __launch_bounds__(256) conv_wfT_kernel(const float* __restrict__ Wf) {
    __shared__ float ts[32][33];
    int d0 = blockIdx.x * 32, n0 = blockIdx.y * 32, l = blockIdx.z;
    int tx = threadIdx.x & 31, ty = threadIdx.x >> 5;
    #pragma unroll
    for (int r = 0; r < 4; r++) {
        int d = d0 + ty + r * 8;
        ts[ty + r * 8][tx] = Wf[((size_t)l * D_ + d) * D_ + n0 + tx];
    }
    __syncthreads();
    #pragma unroll
    for (int r = 0; r < 4; r++) {
        int n = n0 + ty + r * 8;
        g_wfT[((size_t)l * D_ + n) * D_ + d0 + tx] = __float2half(ts[tx][ty + r * 8]);
    }
}
__global__ void build_circ_kernel(const float* __restrict__ alpha) {
    int bid = blockIdx.x;           // h*1024 + i
    int h = bid >> 10, i = bid & 1023;
    const float* a = alpha + (size_t)h * N_;
    size_t base = (size_t)bid * N_;
    #pragma unroll
    for (int t = 0; t < 4; t++) {
        int j = threadIdx.x + t * 256;
        g_cc[base + j] = __float2half(a[(i - j) & (N_ - 1)]);
    }
}

// ---------------------------------------------------------------------------
// Warp-per-row LayerNorm (no smem, shuffle reduction). 8 rows/block.
// ---------------------------------------------------------------------------
__device__ __forceinline__ void warp_stats(const float4* v, float& mu, float& inv) {
    float s = 0.f, q = 0.f;
    #pragma unroll
    for (int i = 0; i < 6; i++) {
        s += v[i].x + v[i].y + v[i].z + v[i].w;
        q += v[i].x*v[i].x + v[i].y*v[i].y + v[i].z*v[i].z + v[i].w*v[i].w;
    }
    #pragma unroll
    for (int o = 16; o; o >>= 1) {
        s += __shfl_xor_sync(0xffffffffu, s, o);
        q += __shfl_xor_sync(0xffffffffu, q, o);
    }
    mu = s * (1.f / D_);
    float var = q * (1.f / D_) - mu * mu;
    inv = rsqrtf(var + EPS_);
}

__global__ void __launch_bounds__(256) ln1_kernel(
    const float* __restrict__ in, const float* __restrict__ scale,
    const float* __restrict__ bias)
{
    int warp = threadIdx.x >> 5, lane = threadIdx.x & 31;
    size_t row = (size_t)blockIdx.x * 8 + warp;
    const float4* p = reinterpret_cast<const float4*>(in + row * D_);
    const float4* sc = reinterpret_cast<const float4*>(scale);
    const float4* bi = reinterpret_cast<const float4*>(bias);
    float4 v[6];
    #pragma unroll
    for (int i = 0; i < 6; i++) v[i] = p[lane + 32 * i];
    float mu, inv;
    warp_stats(v, mu, inv);
    #pragma unroll
    for (int i = 0; i < 6; i++) {
        int g4 = lane + 32 * i;
        float4 s4 = sc[g4], b4 = bi[g4];
        __half2 h0 = __floats2half2_rn((v[i].x - mu) * inv * s4.x + b4.x,
                                       (v[i].y - mu) * inv * s4.y + b4.y);
        __half2 h1 = __floats2half2_rn((v[i].z - mu) * inv * s4.z + b4.z,
                                       (v[i].w - mu) * inv * s4.w + b4.w);
        uint2 u; u.x = *(uint32_t*)&h0; u.y = *(uint32_t*)&h1;
        *reinterpret_cast<uint2*>(g_xn + row * D_ + g4 * 4) = u;
    }
}

// input t is fp16. LAST=0: z = swish(LN(t)) -> g_zh
//                  LAST=1: out = log_cosh(swish(LN(t)) + x1h)
template<int LAST>
__global__ void __launch_bounds__(256) ln_swish_kernel(
    const float* __restrict__ scale, const float* __restrict__ bias,
    float* __restrict__ out)
{
    int warp = threadIdx.x >> 5, lane = threadIdx.x & 31;
    size_t row = (size_t)blockIdx.x * 8 + warp;
    const uint2* p = reinterpret_cast<const uint2*>(g_th + row * D_);
    const float4* sc = reinterpret_cast<const float4*>(scale);
    const float4* bi = reinterpret_cast<const float4*>(bias);
    float4 v[6];
    #pragma unroll
    for (int i = 0; i < 6; i++) {
        uint2 u = p[lane + 32 * i];
        __half2 h0 = *(__half2*)&u.x, h1 = *(__half2*)&u.y;
        float2 f0 = __half22float2(h0), f1 = __half22float2(h1);
        v[i] = make_float4(f0.x, f0.y, f1.x, f1.y);
    }
    float mu, inv;
    warp_stats(v, mu, inv);
    #pragma unroll
    for (int i = 0; i < 6; i++) {
        int g4 = lane + 32 * i;
        float4 s4 = sc[g4], b4 = bi[g4];
        float r[4] = {(v[i].x - mu) * inv * s4.x + b4.x,
                      (v[i].y - mu) * inv * s4.y + b4.y,
                      (v[i].z - mu) * inv * s4.z + b4.z,
                      (v[i].w - mu) * inv * s4.w + b4.w};
        #pragma unroll
        for (int c = 0; c < 4; c++) r[c] = r[c] * (1.f / (1.f + expf(-r[c])));
        if (LAST) {
            uint2 ux = *reinterpret_cast<const uint2*>(g_x1h + row * D_ + g4 * 4);
            float2 xa = __half22float2(*(__half2*)&ux.x);
            float2 xb = __half22float2(*(__half2*)&ux.y);
            float xs[4] = {xa.x, xa.y, xb.x, xb.y};
            float4 o4;
            float* po = &o4.x;
            #pragma unroll
            for (int c = 0; c < 4; c++) {
                float sum = r[c] + xs[c];
                float ax = fabsf(sum);
                po[c] = ax + log1pf(expf(-2.f * ax)) - 0.69314718055994530942f;
            }
            *reinterpret_cast<float4*>(out + row * D_ + g4 * 4) = o4;
        } else {
            __half2 h0 = __floats2half2_rn(r[0], r[1]);
            __half2 h1 = __floats2half2_rn(r[2], r[3]);
            uint2 u; u.x = *(uint32_t*)&h0; u.y = *(uint32_t*)&h1;
            *reinterpret_cast<uint2*>(g_zh + row * D_ + g4 * 4) = u;
        }
    }
}

// ---------------------------------------------------------------------------
// HMMA fp16 GEMM (fp32 accum). Block 128x128, BK=32, 3-stage cp.async,
// 2 CTAs/SM. 8 warps (2m x 4n), warp tile 64x32, m16n8k16.
// MODE 0: GEMM1 -> smem transpose, scatter v [h][b*64+k][j]; tileOff = col-tile
// MODE 1: circ  -> x1h = fp16(x + D); tileOff = head offset; strZ per head
// MODE 2: FFN   -> t = D + bias (fp16)
// ---------------------------------------------------------------------------
#define BM 128
#define BN 128
#define TILE_B   8192u            // 128x32 fp16
#define STAGE_B  (2u*TILE_B)      // A, B
#define NSTAGE   3
#define SMEM_BYTES (NSTAGE*STAGE_B)   // 49152 ; epi buffer 33280 fits

// 64B-row swizzle: 4 chunks of 16B; chunk' = cc ^ ((row>>1)&3)
__device__ __forceinline__ uint32_t sw_off(int row, int cc) {
    return (uint32_t)(row * 64 + ((cc ^ ((row >> 1) & 3)) << 4));
}

__device__ __forceinline__ void cp_tile(uint32_t dstBase, const __half* src,
                                        int rowBase, int kBase, int ld, int tid)
{
    const char* g = (const char*)src + ((size_t)rowBase * ld + kBase) * 2;
    #pragma unroll
    for (int t = 0; t < 2; t++) {
        int ci = tid + t * 256;
        int row = ci >> 2, cc = ci & 3;
        CP_ASYNC(dstBase + sw_off(row, cc), g + (size_t)row * ld * 2 + cc * 16);
    }
}

template<int MODE>
__global__ void __launch_bounds__(256, 2) tc_gemm(
    const __half* __restrict__ A, const __half* __restrict__ Bm,
    int Kdim, size_t strZ,
    const float* __restrict__ xin,            // mode1
    __half* __restrict__ out_h,               // mode0: vc, mode1: x1h, mode2: t
    const float* __restrict__ bias,           // mode2
    int tileOff)                              // mode0: col-tile, mode1: head
{
    extern __shared__ char smem[];
    const int tid = threadIdx.x;
    const int wid = tid >> 5, lane = tid & 31;
    const uint32_t sbase = smem_u32(smem);

    const int mBase = blockIdx.y * BM;
    const int nBase = (blockIdx.x + (MODE == 0 ? tileOff : 0)) * BN;
    const int bz = blockIdx.z;
    const __half* Ab = A  + (size_t)bz * strZ;
    const __half* Bb = Bm + (size_t)bz * strZ;

    const int warpM = wid >> 2;     // 0..1 (x64 rows)
    const int warpN = wid & 3;      // 0..3 (x32 cols)

    const int nc = Kdim >> 5;       // BK = 32

    #pragma unroll
    for (int s = 0; s < NSTAGE - 1; s++) {
        uint32_t sb = sbase + s * STAGE_B;
        cp_tile(sb,          Ab, mBase, s * 32, Kdim, tid);
        cp_tile(sb + TILE_B, Bb, nBase, s * 32, Kdim, tid);
        CP_COMMIT();
    }

    float acc[4][4][4] = {};
    const int lrow = lane & 15;
    const int lsel = lane >> 4;

    for (int c = 0; c < nc; c++) {
        CP_WAIT(NSTAGE - 2);
        __syncthreads();

        int pre = c + NSTAGE - 1;
        if (pre < nc) {
            uint32_t sb = sbase + (pre % NSTAGE) * STAGE_B;
            cp_tile(sb,          Ab, mBase, pre * 32, Kdim, tid);
            cp_tile(sb + TILE_B, Bb, nBase, pre * 32, Kdim, tid);
            CP_COMMIT();
        }

        uint32_t stA = sbase + (c % NSTAGE) * STAGE_B;
        uint32_t stB = stA + TILE_B;

        #pragma unroll
        for (int kk = 0; kk < 2; kk++) {
            int cc = kk * 2 + lsel;
            uint32_t aF[4][4], bF[2][4];
            #pragma unroll
            for (int mt = 0; mt < 4; mt++) {
                int r = warpM * 64 + mt * 16 + lrow;
                ldsm_x4(aF[mt], stA + sw_off(r, cc));
            }
            #pragma unroll
            for (int nt2 = 0; nt2 < 2; nt2++) {
                int r = warpN * 32 + nt2 * 16 + lrow;
                ldsm_x4(bF[nt2], stB + sw_off(r, cc));
            }
            #pragma unroll
            for (int mt = 0; mt < 4; mt++)
                #pragma unroll
                for (int nt = 0; nt < 4; nt++) {
                    uint32_t b0 = bF[nt >> 1][nt & 1];
                    uint32_t b1 = bF[nt >> 1][(nt & 1) + 2];
                    mma16816(acc[mt][nt], aF[mt], b0, b1);
                }
        }
    }
    CP_WAIT(0);

    const int mBaseW = mBase + warpM * 64;
    const int nBaseW = nBase + warpN * 32;

    if (MODE == 0) {
        // two 64-col chunks through smem [128][65], then column writes
        float* sbuf = reinterpret_cast<float*>(smem);
        const int LDS = 65;
        #pragma unroll
        for (int hf = 0; hf < 2; hf++) {
            __syncthreads();
            if ((warpN >> 1) == hf) {
                #pragma unroll
                for (int mt = 0; mt < 4; mt++)
                    #pragma unroll
                    for (int nt = 0; nt < 4; nt++) {
                        int rl = warpM * 64 + mt * 16 + (lane >> 2);
                        int cl = (warpN & 1) * 32 + nt * 8 + ((lane & 3) << 1);
                        sbuf[rl * LDS + cl]           = acc[mt][nt][0];
                        sbuf[rl * LDS + cl + 1]       = acc[mt][nt][1];
                        sbuf[(rl + 8) * LDS + cl]     = acc[mt][nt][2];
                        sbuf[(rl + 8) * LDS + cl + 1] = acc[mt][nt][3];
                    }
            }
            __syncthreads();
            #pragma unroll
            for (int i = 0; i < 8; i++) {
                int cl = wid * 8 + i;
                int cg = nBase + hf * 64 + cl;
                int h = cg >> 6, k = cg & 63;
                #pragma unroll
                for (int q = 0; q < 2; q++) {
                    int m = q * 64 + lane * 2;
                    int mg = mBase + m;
                    int b = mg >> 10, j = mg & 1023;
                    size_t o = (((size_t)(h << 10) + (b << 6) + k) << 10) + j;
                    __half2 hv = __floats2half2_rn(sbuf[m * LDS + cl],
                                                   sbuf[(m + 1) * LDS + cl]);
                    *reinterpret_cast<__half2*>(out_h + o) = hv;
                }
            }
        }
    } else {
        #pragma unroll
        for (int mt = 0; mt < 4; mt++)
            #pragma unroll
            for (int nt = 0; nt < 4; nt++) {
                int i0 = mBaseW + mt * 16 + (lane >> 2);
                int cl = nBaseW + nt * 8 + ((lane & 3) << 1);
                #pragma unroll
                for (int h2 = 0; h2 < 2; h2++) {
                    int i = i0 + h2 * 8;
                    float v0 = acc[mt][nt][h2 * 2];
                    float v1 = acc[mt][nt][h2 * 2 + 1];
                    if (MODE == 1) {
                        int b = cl >> 6, k = cl & 63;
                        size_t o = ((size_t)(b << 10) + i) * D_
                                   + (tileOff + bz) * HS_ + k;
                        *reinterpret_cast<__half2*>(out_h + o) =
                            __floats2half2_rn(xin[o] + v0, xin[o + 1] + v1);
                    } else {
                        size_t o = (size_t)i * D_ + cl;
                        *reinterpret_cast<__half2*>(out_h + o) =
                            __floats2half2_rn(v0 + bias[cl], v1 + bias[cl + 1]);
                    }
                }
            }
    }
}

// ---------------------------------------------------------------------------
// Launch: 3 streams. s2 = circ prep + chunked circ (pipelined behind GEMM1
// column chunks); s3 = Wf prep.
// ---------------------------------------------------------------------------
extern "C" void kernel_launch(void* const* d_in, const int* in_sizes, int n_in,
                              void* d_out, int out_size)
{
    const float* x     = (const float*)d_in[0];
    const float* ln1_s = (const float*)d_in[1];
    const float* ln1_b = (const float*)d_in[2];
    const float* Wv    = (const float*)d_in[3];
    const float* alpha = (const float*)d_in[4];
    const float* Wf    = (const float*)d_in[5];
    const float* bf    = (const float*)d_in[6];
    const float* lnf_s = (const float*)d_in[7];
    const float* lnf_b = (const float*)d_in[8];
    float* out = (float*)d_out;

    static cudaStream_t s2 = nullptr, s3 = nullptr;
    static cudaEvent_t ev0, evWv, evWf, evC, evG[3];
    if (!s2) {
        cudaStreamCreateWithFlags(&s2, cudaStreamNonBlocking);
        cudaStreamCreateWithFlags(&s3, cudaStreamNonBlocking);
        cudaEventCreateWithFlags(&ev0,  cudaEventDisableTiming);
        cudaEventCreateWithFlags(&evWv, cudaEventDisableTiming);
        cudaEventCreateWithFlags(&evWf, cudaEventDisableTiming);
        cudaEventCreateWithFlags(&evC,  cudaEventDisableTiming);
        for (int i = 0; i < 3; i++)
            cudaEventCreateWithFlags(&evG[i], cudaEventDisableTiming);
        cudaFuncSetAttribute(tc_gemm<0>, cudaFuncAttributeMaxDynamicSharedMemorySize, SMEM_BYTES);
        cudaFuncSetAttribute(tc_gemm<1>, cudaFuncAttributeMaxDynamicSharedMemorySize, SMEM_BYTES);
        cudaFuncSetAttribute(tc_gemm<2>, cudaFuncAttributeMaxDynamicSharedMemorySize, SMEM_BYTES);
    }

    __half *xn, *wvT, *wfT, *vc, *cc, *x1h, *th, *zh;
    cudaGetSymbolAddress((void**)&xn, g_xn);
    cudaGetSymbolAddress((void**)&wvT, g_wvT);
    cudaGetSymbolAddress((void**)&wfT, g_wfT);
    cudaGetSymbolAddress((void**)&vc, g_vc);
    cudaGetSymbolAddress((void**)&cc, g_cc);
    cudaGetSymbolAddress((void**)&x1h, g_x1h);
    cudaGetSymbolAddress((void**)&th, g_th);
    cudaGetSymbolAddress((void**)&zh, g_zh);

    // fork prep
    cudaEventRecord(ev0, 0);
    cudaStreamWaitEvent(s2, ev0, 0);
    cudaStreamWaitEvent(s3, ev0, 0);
    conv_wvT_kernel<<<dim3(D_/32, HS_/32, H_), 256, 0, s2>>>(Wv);
    cudaEventRecord(evWv, s2);
    build_circ_kernel<<<H_*N_, 256, 0, s2>>>(alpha);
    conv_wfT_kernel<<<dim3(D_/32, D_/32, L_), 256, 0, s3>>>(Wf);
    cudaEventRecord(evWf, s3);

    // main: LN1
    ln1_kernel<<<M_/8, 256>>>(x, ln1_s, ln1_b);
    cudaStreamWaitEvent(0, evWv, 0);

    // GEMM1 column chunks (4 heads each) pipelined with circ chunks on s2
    for (int c = 0; c < 3; c++) {
        tc_gemm<0><<<dim3(2, M_/BM, 1), 256, SMEM_BYTES>>>(
            xn, wvT, D_, 0, nullptr, vc, nullptr, 2 * c);
        cudaEventRecord(evG[c], 0);
        cudaStreamWaitEvent(s2, evG[c], 0);
        tc_gemm<1><<<dim3(N_/BN, N_/BM, 4), 256, SMEM_BYTES, s2>>>(
            cc + (size_t)4 * c * N_ * N_, vc + (size_t)4 * c * N_ * N_,
            N_, (size_t)N_ * N_, x, x1h, nullptr, 4 * c);
    }
    cudaEventRecord(evC, s2);

    // FFN (waits on circ + Wf prep)
    cudaStreamWaitEvent(0, evC, 0);
    cudaStreamWaitEvent(0, evWf, 0);
    tc_gemm<2><<<dim3(D_/BN, M_/BM, 1), 256, SMEM_BYTES>>>(
        x1h, wfT, D_, 0, nullptr, th, bf, 0);
    ln_swish_kernel<0><<<M_/8, 256>>>(lnf_s, lnf_b, nullptr);

    tc_gemm<2><<<dim3(D_/BN, M_/BM, 1), 256, SMEM_BYTES>>>(
        zh, wfT + (size_t)D_*D_, D_, 0, nullptr, th, bf + D_, 0);
    ln_swish_kernel<1><<<M_/8, 256>>>(lnf_s + D_, lnf_b + D_, out);
}